// round 6
// baseline (speedup 1.0000x reference)
#include <cuda_runtime.h>
#include <cuda_fp16.h>
#include <math_constants.h>

#define Nn 50000
#define Dd 128
#define Ee 800000
#define CAP 64
#define LRELU_ALPHA 0.2f

// Scratch (device globals -- no allocation allowed).
// INVARIANT: g_cnt is all-zero at every kernel_launch entry (zero-initialized
// at load; k_node restores it to zero every run).
__device__ __align__(16) __half g_Whh[(size_t)Nn * Dd];  // 12.8 MB, L2-resident
__device__ float g_sv[Nn];
__device__ float g_dv[Nn];
__device__ int   g_cnt[Nn];
__device__ int   g_srcs[(size_t)Nn * CAP];               // direct-mapped CSR

__device__ __forceinline__ unsigned tf32(float f) {
    unsigned u; asm("cvt.rna.tf32.f32 %0, %1;" : "=r"(u) : "f"(f)); return u;
}
__device__ __forceinline__ void mma_tf32(float c[4], const unsigned a[4], const unsigned b[2]) {
    asm volatile(
        "mma.sync.aligned.m16n8k8.row.col.f32.tf32.tf32.f32 "
        "{%0,%1,%2,%3}, {%4,%5,%6,%7}, {%8,%9}, {%0,%1,%2,%3};"
        : "+f"(c[0]), "+f"(c[1]), "+f"(c[2]), "+f"(c[3])
        : "r"(a[0]), "r"(a[1]), "r"(a[2]), "r"(a[3]), "r"(b[0]), "r"(b[1]));
}

// ---------------------------------------------------------------------------
// K1: direct-mapped CSR scatter, 4 edges/thread for atomic MLP
// ---------------------------------------------------------------------------
__global__ void k_scatter(const int4* __restrict__ src4, const int4* __restrict__ dst4) {
    int i = blockIdx.x * blockDim.x + threadIdx.x;
    if (i >= Ee / 4) return;
    int4 s = src4[i], d = dst4[i];
    int sl;
    sl = atomicAdd(&g_cnt[d.x], 1); if (sl < CAP) g_srcs[d.x * CAP + sl] = s.x;
    sl = atomicAdd(&g_cnt[d.y], 1); if (sl < CAP) g_srcs[d.y * CAP + sl] = s.y;
    sl = atomicAdd(&g_cnt[d.z], 1); if (sl < CAP) g_srcs[d.z * CAP + sl] = s.z;
    sl = atomicAdd(&g_cnt[d.w], 1); if (sl < CAP) g_srcs[d.w * CAP + sl] = s.w;
}

// ---------------------------------------------------------------------------
// K2: Wh = h @ W via tf32 mma (tensor pipe), Wh stored fp16, sv/dv fused.
// ---------------------------------------------------------------------------
#define NTILES 3125   // 50000 / 16
__global__ __launch_bounds__(128, 2)
void k_gemm(const float* __restrict__ h, const float* __restrict__ W,
            const float* __restrict__ a) {
    __shared__ __align__(16) float sh[16][132];
    __shared__ float ssv[4][16], sdv[4][16];
    const int lane  = threadIdx.x & 31;
    const int wn    = threadIdx.x >> 5;
    const int ncol0 = wn * 32;
    const int r     = lane >> 2;
    const int cc    = 2 * (lane & 3);

    unsigned b[16][4][2];
#pragma unroll
    for (int ks = 0; ks < 16; ks++)
#pragma unroll
        for (int j = 0; j < 4; j++) {
            int n  = ncol0 + j * 8 + (lane >> 2);
            int k0 = ks * 8 + (lane & 3);
            b[ks][j][0] = tf32(W[k0 * Dd + n]);
            b[ks][j][1] = tf32(W[(k0 + 4) * Dd + n]);
        }
    float2 as[4], ad[4];
#pragma unroll
    for (int j = 0; j < 4; j++) {
        int col = ncol0 + j * 8 + cc;
        as[j] = make_float2(a[col], a[col + 1]);
        ad[j] = make_float2(a[Dd + col], a[Dd + col + 1]);
    }

    for (int tile = blockIdx.x; tile < NTILES; tile += gridDim.x) {
        const int base = tile * 16;

        const float4* hsrc = (const float4*)(h + (size_t)base * Dd);
#pragma unroll
        for (int t = 0; t < 4; t++) {
            int idx = threadIdx.x + t * 128;
            int rr = idx >> 5, c2 = idx & 31;
            *(float4*)&sh[rr][c2 * 4] = hsrc[idx];
        }
        __syncthreads();

        float c[4][4];
#pragma unroll
        for (int j = 0; j < 4; j++)
#pragma unroll
            for (int q = 0; q < 4; q++) c[j][q] = 0.0f;

#pragma unroll
        for (int ks = 0; ks < 16; ks++) {
            const int kc = ks * 8 + (lane & 3);
            unsigned av[4];
            av[0] = tf32(sh[r][kc]);
            av[1] = tf32(sh[r + 8][kc]);
            av[2] = tf32(sh[r][kc + 4]);
            av[3] = tf32(sh[r + 8][kc + 4]);
#pragma unroll
            for (int j = 0; j < 4; j++) mma_tf32(c[j], av, b[ks][j]);
        }

        float vs0 = 0.f, vs1 = 0.f, vd0 = 0.f, vd1 = 0.f;
#pragma unroll
        for (int j = 0; j < 4; j++) {
            int col = ncol0 + j * 8 + cc;
            *(__half2*)&g_Whh[(size_t)(base + r) * Dd + col] =
                __floats2half2_rn(c[j][0], c[j][1]);
            *(__half2*)&g_Whh[(size_t)(base + r + 8) * Dd + col] =
                __floats2half2_rn(c[j][2], c[j][3]);
            vs0 = fmaf(c[j][0], as[j].x, fmaf(c[j][1], as[j].y, vs0));
            vs1 = fmaf(c[j][2], as[j].x, fmaf(c[j][3], as[j].y, vs1));
            vd0 = fmaf(c[j][0], ad[j].x, fmaf(c[j][1], ad[j].y, vd0));
            vd1 = fmaf(c[j][2], ad[j].x, fmaf(c[j][3], ad[j].y, vd1));
        }
#pragma unroll
        for (int off = 1; off <= 2; off <<= 1) {
            vs0 += __shfl_xor_sync(0xffffffffu, vs0, off);
            vs1 += __shfl_xor_sync(0xffffffffu, vs1, off);
            vd0 += __shfl_xor_sync(0xffffffffu, vd0, off);
            vd1 += __shfl_xor_sync(0xffffffffu, vd1, off);
        }
        if ((lane & 3) == 0) {
            ssv[wn][r] = vs0; ssv[wn][r + 8] = vs1;
            sdv[wn][r] = vd0; sdv[wn][r + 8] = vd1;
        }
        __syncthreads();
        if (threadIdx.x < 16) {
            int t = threadIdx.x;
            g_sv[base + t] = ssv[0][t] + ssv[1][t] + ssv[2][t] + ssv[3][t];
        } else if (threadIdx.x >= 32 && threadIdx.x < 48) {
            int t = threadIdx.x - 32;
            g_dv[base + t] = sdv[0][t] + sdv[1][t] + sdv[2][t] + sdv[3][t];
        }
    }
}

// ---------------------------------------------------------------------------
// K3: fused per-node softmax + aggregation + residual. One warp per node.
// Gather: LDG.128, 16 lanes per edge, two edges per warp-iteration
// (half-warp hw handles edges 2i+hw). Stage holds (alpha, row byte-offset).
// Also restores g_cnt to zero (removes the reset kernel).
// ---------------------------------------------------------------------------
__global__ __launch_bounds__(256)
void k_node(const float* __restrict__ h, float* __restrict__ out) {
    __shared__ float2 stage[8][CAP];
    const int warp = threadIdx.x >> 5;
    const int lane = threadIdx.x & 31;
    const int v    = blockIdx.x * 8 + warp;
    if (v >= Nn) return;

    int cnt = g_cnt[v];
    if (lane == 0) g_cnt[v] = 0;          // restore invariant for next run
    cnt = cnt < CAP ? cnt : CAP;

    const int q  = lane & 15;             // column block (16 B each)
    const int hw = lane >> 4;             // edge parity

    float4 acc0 = make_float4(0.f, 0.f, 0.f, 0.f);
    float4 acc1 = make_float4(0.f, 0.f, 0.f, 0.f);

    if (cnt > 0) {
        const float dvv = g_dv[v];
        const int* sp = g_srcs + v * CAP;

        int s0 = 0, s1 = 0;
        float e0 = -CUDART_INF_F, e1 = -CUDART_INF_F;
        if (lane < cnt) {
            s0 = sp[lane];
            float e = g_sv[s0] + dvv;
            e0 = (e > 0.0f) ? e : LRELU_ALPHA * e;
        }
        if (lane + 32 < cnt) {
            s1 = sp[lane + 32];
            float e = g_sv[s1] + dvv;
            e1 = (e > 0.0f) ? e : LRELU_ALPHA * e;
        }

        float m = fmaxf(e0, e1);
#pragma unroll
        for (int off = 16; off; off >>= 1)
            m = fmaxf(m, __shfl_xor_sync(0xffffffffu, m, off));

        float ex0 = (lane < cnt)      ? __expf(e0 - m) : 0.0f;
        float ex1 = (lane + 32 < cnt) ? __expf(e1 - m) : 0.0f;
        float sum = ex0 + ex1;
#pragma unroll
        for (int off = 16; off; off >>= 1)
            sum += __shfl_xor_sync(0xffffffffu, sum, off);
        const float inv = 1.0f / sum;

        // (alpha, row byte offset). Entries >= cnt carry alpha=0, off=0.
        stage[warp][lane]      = make_float2(ex0 * inv, __int_as_float(s0 << 8));
        stage[warp][lane + 32] = make_float2(ex1 * inv, __int_as_float(s1 << 8));
        __syncwarp();

        const char* whbase = (const char*)g_Whh + q * 16;
        const int niter = (cnt + 1) >> 1;
#pragma unroll 2
        for (int i = 0; i < niter; i++) {
            float2 p = stage[warp][2 * i + hw];
            uint4 u = *(const uint4*)(whbase + __float_as_int(p.y));
            float2 f0 = __half22float2(*(__half2*)&u.x);
            float2 f1 = __half22float2(*(__half2*)&u.y);
            float2 f2 = __half22float2(*(__half2*)&u.z);
            float2 f3 = __half22float2(*(__half2*)&u.w);
            acc0.x = fmaf(p.x, f0.x, acc0.x);
            acc0.y = fmaf(p.x, f0.y, acc0.y);
            acc0.z = fmaf(p.x, f1.x, acc0.z);
            acc0.w = fmaf(p.x, f1.y, acc0.w);
            acc1.x = fmaf(p.x, f2.x, acc1.x);
            acc1.y = fmaf(p.x, f2.y, acc1.y);
            acc1.z = fmaf(p.x, f3.x, acc1.z);
            acc1.w = fmaf(p.x, f3.y, acc1.w);
        }
    }

    // combine the two half-warps' edge subsets (same columns)
    acc0.x += __shfl_down_sync(0xffffffffu, acc0.x, 16);
    acc0.y += __shfl_down_sync(0xffffffffu, acc0.y, 16);
    acc0.z += __shfl_down_sync(0xffffffffu, acc0.z, 16);
    acc0.w += __shfl_down_sync(0xffffffffu, acc0.w, 16);
    acc1.x += __shfl_down_sync(0xffffffffu, acc1.x, 16);
    acc1.y += __shfl_down_sync(0xffffffffu, acc1.y, 16);
    acc1.z += __shfl_down_sync(0xffffffffu, acc1.z, 16);
    acc1.w += __shfl_down_sync(0xffffffffu, acc1.w, 16);

    if (hw == 0) {
        const float4* hr = (const float4*)(h + (size_t)v * Dd) + q * 2;
        float4 r0 = hr[0], r1 = hr[1];
        acc0.x += r0.x; acc0.y += r0.y; acc0.z += r0.z; acc0.w += r0.w;
        acc1.x += r1.x; acc1.y += r1.y; acc1.z += r1.z; acc1.w += r1.w;
        float4* o = (float4*)(out + (size_t)v * Dd) + q * 2;
        o[0] = acc0;
        o[1] = acc1;
    }
}

// ---------------------------------------------------------------------------
extern "C" void kernel_launch(void* const* d_in, const int* in_sizes, int n_in,
                              void* d_out, int out_size) {
    const float* h   = (const float*)d_in[0];
    const float* W   = (const float*)d_in[1];
    const float* a   = (const float*)d_in[2];
    const int*   src = (const int*)d_in[3];
    const int*   dst = (const int*)d_in[4];
    float*       out = (float*)d_out;

    k_scatter<<<(Ee / 4 + 255) / 256, 256>>>((const int4*)src, (const int4*)dst);
    k_gemm   <<<296, 128>>>(h, W, a);
    k_node   <<<(Nn + 7) / 8, 256>>>(h, out);
}

// round 7
// speedup vs baseline: 1.1923x; 1.1923x over previous
#include <cuda_runtime.h>
#include <cuda_fp16.h>
#include <math_constants.h>

#define Nn 50000
#define Dd 128
#define Ee 800000
#define CAP 64
#define LRELU_ALPHA 0.2f

// Scratch (device globals -- no allocation allowed).
// INVARIANT: g_cnt is all-zero at every kernel_launch entry (zero-initialized
// at load; k_node restores it to zero every run).
__device__ __align__(16) __half g_Whh[(size_t)Nn * Dd];  // 12.8 MB, L2-resident
__device__ float g_sv[Nn];
__device__ float g_dv[Nn];
__device__ int   g_cnt[Nn];
__device__ int   g_srcs[(size_t)Nn * CAP];               // direct-mapped CSR

__device__ __forceinline__ unsigned tf32(float f) {
    unsigned u; asm("cvt.rna.tf32.f32 %0, %1;" : "=r"(u) : "f"(f)); return u;
}
__device__ __forceinline__ void mma_tf32(float c[4], const unsigned a[4], const unsigned b[2]) {
    asm volatile(
        "mma.sync.aligned.m16n8k8.row.col.f32.tf32.tf32.f32 "
        "{%0,%1,%2,%3}, {%4,%5,%6,%7}, {%8,%9}, {%0,%1,%2,%3};"
        : "+f"(c[0]), "+f"(c[1]), "+f"(c[2]), "+f"(c[3])
        : "r"(a[0]), "r"(a[1]), "r"(a[2]), "r"(a[3]), "r"(b[0]), "r"(b[1]));
}

// ---------------------------------------------------------------------------
// K1: direct-mapped CSR scatter, 4 edges/thread for atomic MLP
// ---------------------------------------------------------------------------
__global__ void k_scatter(const int4* __restrict__ src4, const int4* __restrict__ dst4) {
    int i = blockIdx.x * blockDim.x + threadIdx.x;
    if (i >= Ee / 4) return;
    int4 s = src4[i], d = dst4[i];
    int sl;
    sl = atomicAdd(&g_cnt[d.x], 1); if (sl < CAP) g_srcs[d.x * CAP + sl] = s.x;
    sl = atomicAdd(&g_cnt[d.y], 1); if (sl < CAP) g_srcs[d.y * CAP + sl] = s.y;
    sl = atomicAdd(&g_cnt[d.z], 1); if (sl < CAP) g_srcs[d.z * CAP + sl] = s.z;
    sl = atomicAdd(&g_cnt[d.w], 1); if (sl < CAP) g_srcs[d.w * CAP + sl] = s.w;
}

// ---------------------------------------------------------------------------
// K2: Wh = h @ W via tf32 mma (tensor pipe), Wh stored fp16, sv/dv fused.
// ---------------------------------------------------------------------------
#define NTILES 3125   // 50000 / 16
__global__ __launch_bounds__(128, 2)
void k_gemm(const float* __restrict__ h, const float* __restrict__ W,
            const float* __restrict__ a) {
    __shared__ __align__(16) float sh[16][132];
    __shared__ float ssv[4][16], sdv[4][16];
    const int lane  = threadIdx.x & 31;
    const int wn    = threadIdx.x >> 5;
    const int ncol0 = wn * 32;
    const int r     = lane >> 2;
    const int cc    = 2 * (lane & 3);

    unsigned b[16][4][2];
#pragma unroll
    for (int ks = 0; ks < 16; ks++)
#pragma unroll
        for (int j = 0; j < 4; j++) {
            int n  = ncol0 + j * 8 + (lane >> 2);
            int k0 = ks * 8 + (lane & 3);
            b[ks][j][0] = tf32(W[k0 * Dd + n]);
            b[ks][j][1] = tf32(W[(k0 + 4) * Dd + n]);
        }
    float2 as[4], ad[4];
#pragma unroll
    for (int j = 0; j < 4; j++) {
        int col = ncol0 + j * 8 + cc;
        as[j] = make_float2(a[col], a[col + 1]);
        ad[j] = make_float2(a[Dd + col], a[Dd + col + 1]);
    }

    for (int tile = blockIdx.x; tile < NTILES; tile += gridDim.x) {
        const int base = tile * 16;

        const float4* hsrc = (const float4*)(h + (size_t)base * Dd);
#pragma unroll
        for (int t = 0; t < 4; t++) {
            int idx = threadIdx.x + t * 128;
            int rr = idx >> 5, c2 = idx & 31;
            *(float4*)&sh[rr][c2 * 4] = hsrc[idx];
        }
        __syncthreads();

        float c[4][4];
#pragma unroll
        for (int j = 0; j < 4; j++)
#pragma unroll
            for (int q = 0; q < 4; q++) c[j][q] = 0.0f;

#pragma unroll
        for (int ks = 0; ks < 16; ks++) {
            const int kc = ks * 8 + (lane & 3);
            unsigned av[4];
            av[0] = tf32(sh[r][kc]);
            av[1] = tf32(sh[r + 8][kc]);
            av[2] = tf32(sh[r][kc + 4]);
            av[3] = tf32(sh[r + 8][kc + 4]);
#pragma unroll
            for (int j = 0; j < 4; j++) mma_tf32(c[j], av, b[ks][j]);
        }

        float vs0 = 0.f, vs1 = 0.f, vd0 = 0.f, vd1 = 0.f;
#pragma unroll
        for (int j = 0; j < 4; j++) {
            int col = ncol0 + j * 8 + cc;
            *(__half2*)&g_Whh[(size_t)(base + r) * Dd + col] =
                __floats2half2_rn(c[j][0], c[j][1]);
            *(__half2*)&g_Whh[(size_t)(base + r + 8) * Dd + col] =
                __floats2half2_rn(c[j][2], c[j][3]);
            vs0 = fmaf(c[j][0], as[j].x, fmaf(c[j][1], as[j].y, vs0));
            vs1 = fmaf(c[j][2], as[j].x, fmaf(c[j][3], as[j].y, vs1));
            vd0 = fmaf(c[j][0], ad[j].x, fmaf(c[j][1], ad[j].y, vd0));
            vd1 = fmaf(c[j][2], ad[j].x, fmaf(c[j][3], ad[j].y, vd1));
        }
#pragma unroll
        for (int off = 1; off <= 2; off <<= 1) {
            vs0 += __shfl_xor_sync(0xffffffffu, vs0, off);
            vs1 += __shfl_xor_sync(0xffffffffu, vs1, off);
            vd0 += __shfl_xor_sync(0xffffffffu, vd0, off);
            vd1 += __shfl_xor_sync(0xffffffffu, vd1, off);
        }
        if ((lane & 3) == 0) {
            ssv[wn][r] = vs0; ssv[wn][r + 8] = vs1;
            sdv[wn][r] = vd0; sdv[wn][r + 8] = vd1;
        }
        __syncthreads();
        if (threadIdx.x < 16) {
            int t = threadIdx.x;
            g_sv[base + t] = ssv[0][t] + ssv[1][t] + ssv[2][t] + ssv[3][t];
        } else if (threadIdx.x >= 32 && threadIdx.x < 48) {
            int t = threadIdx.x - 32;
            g_dv[base + t] = sdv[0][t] + sdv[1][t] + sdv[2][t] + sdv[3][t];
        }
    }
}

// ---------------------------------------------------------------------------
// K3: fused per-node softmax + aggregation + residual. One warp per node.
// Round-5 proven gather structure (uint2/lane, 4 loads per iteration);
// stage padded to a multiple of 4 with alpha=0 entries so the loop has no
// tail; #pragma unroll 2 doubles in-flight loads to 8 (MLP=8).
// Also restores g_cnt to zero (no reset kernel).
// ---------------------------------------------------------------------------
__global__ __launch_bounds__(256)
void k_node(const float* __restrict__ h, float* __restrict__ out) {
    __shared__ float2 stage[8][CAP];
    const int warp = threadIdx.x >> 5;
    const int lane = threadIdx.x & 31;
    const int v    = blockIdx.x * 8 + warp;
    if (v >= Nn) return;

    float4 acc = ((const float4*)h)[v * 32 + lane];  // residual
    int cnt = g_cnt[v];
    if (lane == 0) g_cnt[v] = 0;          // restore invariant for next run
    cnt = cnt < CAP ? cnt : CAP;

    if (cnt > 0) {
        const float dvv = g_dv[v];
        const int* sp = g_srcs + v * CAP;

        int s0 = 0, s1 = 0;
        float e0 = -CUDART_INF_F, e1 = -CUDART_INF_F;
        if (lane < cnt) {
            s0 = sp[lane];
            float e = g_sv[s0] + dvv;
            e0 = (e > 0.0f) ? e : LRELU_ALPHA * e;
        }
        if (lane + 32 < cnt) {
            s1 = sp[lane + 32];
            float e = g_sv[s1] + dvv;
            e1 = (e > 0.0f) ? e : LRELU_ALPHA * e;
        }

        float m = fmaxf(e0, e1);
#pragma unroll
        for (int off = 16; off; off >>= 1)
            m = fmaxf(m, __shfl_xor_sync(0xffffffffu, m, off));

        float ex0 = (lane < cnt)      ? __expf(e0 - m) : 0.0f;
        float ex1 = (lane + 32 < cnt) ? __expf(e1 - m) : 0.0f;
        float sum = ex0 + ex1;
#pragma unroll
        for (int off = 16; off; off >>= 1)
            sum += __shfl_xor_sync(0xffffffffu, sum, off);
        const float inv = 1.0f / sum;

        // all 64 stage entries written; entries >= cnt carry alpha=0, src=0
        stage[warp][lane]      = make_float2(ex0 * inv, __int_as_float(s0));
        stage[warp][lane + 32] = make_float2(ex1 * inv, __int_as_float(s1));
        __syncwarp();

        const uint2* Whh = (const uint2*)g_Whh;   // 8B = 4 halfs per lane
        const int cnt4 = (cnt + 3) & ~3;          // padded: no tail loop
#pragma unroll 2
        for (int i = 0; i < cnt4; i += 4) {
            float2 p0 = stage[warp][i + 0];
            float2 p1 = stage[warp][i + 1];
            float2 p2 = stage[warp][i + 2];
            float2 p3 = stage[warp][i + 3];
            uint2 u0 = Whh[__float_as_int(p0.y) * 32 + lane];
            uint2 u1 = Whh[__float_as_int(p1.y) * 32 + lane];
            uint2 u2 = Whh[__float_as_int(p2.y) * 32 + lane];
            uint2 u3 = Whh[__float_as_int(p3.y) * 32 + lane];
#define ACC(u, al)                                                         \
            {                                                              \
                float2 lo = __half22float2(*(__half2*)&(u).x);             \
                float2 hi = __half22float2(*(__half2*)&(u).y);             \
                acc.x = fmaf((al), lo.x, acc.x);                           \
                acc.y = fmaf((al), lo.y, acc.y);                           \
                acc.z = fmaf((al), hi.x, acc.z);                           \
                acc.w = fmaf((al), hi.y, acc.w);                           \
            }
            ACC(u0, p0.x) ACC(u1, p1.x) ACC(u2, p2.x) ACC(u3, p3.x)
#undef ACC
        }
    }

    ((float4*)out)[v * 32 + lane] = acc;
}

// ---------------------------------------------------------------------------
extern "C" void kernel_launch(void* const* d_in, const int* in_sizes, int n_in,
                              void* d_out, int out_size) {
    const float* h   = (const float*)d_in[0];
    const float* W   = (const float*)d_in[1];
    const float* a   = (const float*)d_in[2];
    const int*   src = (const int*)d_in[3];
    const int*   dst = (const int*)d_in[4];
    float*       out = (float*)d_out;

    k_scatter<<<(Ee / 4 + 255) / 256, 256>>>((const int4*)src, (const int4*)dst);
    k_gemm   <<<296, 128>>>(h, W, a);
    k_node   <<<(Nn + 7) / 8, 256>>>(h, out);
}

// round 8
// speedup vs baseline: 2.0000x; 1.6775x over previous
#include <cuda_runtime.h>
#include <cuda_fp16.h>
#include <math_constants.h>

#define Nn 50000
#define Dd 128
#define Ee 800000
#define CAP 64
#define LRELU_ALPHA 0.2f

#define GEMM_BLOCKS 296   // persistent gemm blocks (2 per SM)
#define NTILES 3125       // 50000 / 16

// Scratch (device globals -- no allocation allowed)
__device__ __align__(16) __half g_Whh[(size_t)Nn * Dd];  // 12.8 MB, L2-resident
__device__ float g_sv[Nn];
__device__ float g_dv[Nn];
__device__ int   g_cnt[Nn];
__device__ int   g_srcs[(size_t)Nn * CAP];               // direct-mapped CSR

__device__ __forceinline__ unsigned tf32(float f) {
    unsigned u; asm("cvt.rna.tf32.f32 %0, %1;" : "=r"(u) : "f"(f)); return u;
}
__device__ __forceinline__ void mma_tf32(float c[4], const unsigned a[4], const unsigned b[2]) {
    asm volatile(
        "mma.sync.aligned.m16n8k8.row.col.f32.tf32.tf32.f32 "
        "{%0,%1,%2,%3}, {%4,%5,%6,%7}, {%8,%9}, {%0,%1,%2,%3};"
        : "+f"(c[0]), "+f"(c[1]), "+f"(c[2]), "+f"(c[3])
        : "r"(a[0]), "r"(a[1]), "r"(a[2]), "r"(a[3]), "r"(b[0]), "r"(b[1]));
}

// ---------------------------------------------------------------------------
// K0: zero in-degree counters (must complete before scatter atomics)
// ---------------------------------------------------------------------------
__global__ void k_reset() {
    int i = blockIdx.x * blockDim.x + threadIdx.x;
    if (i < Nn) g_cnt[i] = 0;
}

// ---------------------------------------------------------------------------
// K1: FUSED gemm + scatter. Even blocks: persistent tf32-mma gemm (exact R5
// structure, Wh stored fp16, sv/dv fused in epilogue). Odd blocks: grid-stride
// CSR scatter (latency-bound, overlaps with the compute-bound gemm on the
// same SMs). No data dependency between the two roles.
// ---------------------------------------------------------------------------
__global__ __launch_bounds__(128, 2)
void k_build(const float* __restrict__ h, const float* __restrict__ W,
             const float* __restrict__ a,
             const int4* __restrict__ src4, const int4* __restrict__ dst4) {
    if (blockIdx.x & 1) {
        // ----- scatter role: 4 edges per int4, grid-stride -----
        const int stride = GEMM_BLOCKS * 128;
        for (int i = (blockIdx.x >> 1) * 128 + threadIdx.x; i < Ee / 4; i += stride) {
            int4 s = src4[i], d = dst4[i];
            int sl;
            sl = atomicAdd(&g_cnt[d.x], 1); if (sl < CAP) g_srcs[d.x * CAP + sl] = s.x;
            sl = atomicAdd(&g_cnt[d.y], 1); if (sl < CAP) g_srcs[d.y * CAP + sl] = s.y;
            sl = atomicAdd(&g_cnt[d.z], 1); if (sl < CAP) g_srcs[d.z * CAP + sl] = s.z;
            sl = atomicAdd(&g_cnt[d.w], 1); if (sl < CAP) g_srcs[d.w * CAP + sl] = s.w;
        }
        return;
    }

    // ----- gemm role (unchanged from the 60.1us kernel) -----
    __shared__ __align__(16) float sh[16][132];
    __shared__ float ssv[4][16], sdv[4][16];
    const int lane  = threadIdx.x & 31;
    const int wn    = threadIdx.x >> 5;
    const int ncol0 = wn * 32;
    const int r     = lane >> 2;
    const int cc    = 2 * (lane & 3);

    unsigned b[16][4][2];
#pragma unroll
    for (int ks = 0; ks < 16; ks++)
#pragma unroll
        for (int j = 0; j < 4; j++) {
            int n  = ncol0 + j * 8 + (lane >> 2);
            int k0 = ks * 8 + (lane & 3);
            b[ks][j][0] = tf32(W[k0 * Dd + n]);
            b[ks][j][1] = tf32(W[(k0 + 4) * Dd + n]);
        }
    float2 as[4], ad[4];
#pragma unroll
    for (int j = 0; j < 4; j++) {
        int col = ncol0 + j * 8 + cc;
        as[j] = make_float2(a[col], a[col + 1]);
        ad[j] = make_float2(a[Dd + col], a[Dd + col + 1]);
    }

    for (int tile = (blockIdx.x >> 1); tile < NTILES; tile += GEMM_BLOCKS) {
        const int base = tile * 16;

        const float4* hsrc = (const float4*)(h + (size_t)base * Dd);
#pragma unroll
        for (int t = 0; t < 4; t++) {
            int idx = threadIdx.x + t * 128;
            int rr = idx >> 5, c2 = idx & 31;
            *(float4*)&sh[rr][c2 * 4] = hsrc[idx];
        }
        __syncthreads();

        float c[4][4];
#pragma unroll
        for (int j = 0; j < 4; j++)
#pragma unroll
            for (int q = 0; q < 4; q++) c[j][q] = 0.0f;

#pragma unroll
        for (int ks = 0; ks < 16; ks++) {
            const int kc = ks * 8 + (lane & 3);
            unsigned av[4];
            av[0] = tf32(sh[r][kc]);
            av[1] = tf32(sh[r + 8][kc]);
            av[2] = tf32(sh[r][kc + 4]);
            av[3] = tf32(sh[r + 8][kc + 4]);
#pragma unroll
            for (int j = 0; j < 4; j++) mma_tf32(c[j], av, b[ks][j]);
        }

        float vs0 = 0.f, vs1 = 0.f, vd0 = 0.f, vd1 = 0.f;
#pragma unroll
        for (int j = 0; j < 4; j++) {
            int col = ncol0 + j * 8 + cc;
            *(__half2*)&g_Whh[(size_t)(base + r) * Dd + col] =
                __floats2half2_rn(c[j][0], c[j][1]);
            *(__half2*)&g_Whh[(size_t)(base + r + 8) * Dd + col] =
                __floats2half2_rn(c[j][2], c[j][3]);
            vs0 = fmaf(c[j][0], as[j].x, fmaf(c[j][1], as[j].y, vs0));
            vs1 = fmaf(c[j][2], as[j].x, fmaf(c[j][3], as[j].y, vs1));
            vd0 = fmaf(c[j][0], ad[j].x, fmaf(c[j][1], ad[j].y, vd0));
            vd1 = fmaf(c[j][2], ad[j].x, fmaf(c[j][3], ad[j].y, vd1));
        }
#pragma unroll
        for (int off = 1; off <= 2; off <<= 1) {
            vs0 += __shfl_xor_sync(0xffffffffu, vs0, off);
            vs1 += __shfl_xor_sync(0xffffffffu, vs1, off);
            vd0 += __shfl_xor_sync(0xffffffffu, vd0, off);
            vd1 += __shfl_xor_sync(0xffffffffu, vd1, off);
        }
        if ((lane & 3) == 0) {
            ssv[wn][r] = vs0; ssv[wn][r + 8] = vs1;
            sdv[wn][r] = vd0; sdv[wn][r + 8] = vd1;
        }
        __syncthreads();
        if (threadIdx.x < 16) {
            int t = threadIdx.x;
            g_sv[base + t] = ssv[0][t] + ssv[1][t] + ssv[2][t] + ssv[3][t];
        } else if (threadIdx.x >= 32 && threadIdx.x < 48) {
            int t = threadIdx.x - 32;
            g_dv[base + t] = sdv[0][t] + sdv[1][t] + sdv[2][t] + sdv[3][t];
        }
    }
}

// ---------------------------------------------------------------------------
// K2: fused per-node softmax + aggregation + residual. One warp per node.
// EXACT structure of the measured-best (27.4us) round-5 kernel.
// ---------------------------------------------------------------------------
__global__ __launch_bounds__(256)
void k_node(const float* __restrict__ h, float* __restrict__ out) {
    __shared__ float2 stage[8][CAP];
    const int warp = threadIdx.x >> 5;
    const int lane = threadIdx.x & 31;
    const int v    = blockIdx.x * 8 + warp;
    if (v >= Nn) return;

    float4 acc = ((const float4*)h)[v * 32 + lane];  // residual
    int cnt = g_cnt[v];
    cnt = cnt < CAP ? cnt : CAP;

    if (cnt > 0) {
        const float dvv = g_dv[v];
        const int* sp = g_srcs + v * CAP;

        int s0 = 0, s1 = 0;
        float e0 = -CUDART_INF_F, e1 = -CUDART_INF_F;
        if (lane < cnt) {
            s0 = sp[lane];
            float e = g_sv[s0] + dvv;
            e0 = (e > 0.0f) ? e : LRELU_ALPHA * e;
        }
        if (lane + 32 < cnt) {
            s1 = sp[lane + 32];
            float e = g_sv[s1] + dvv;
            e1 = (e > 0.0f) ? e : LRELU_ALPHA * e;
        }

        float m = fmaxf(e0, e1);
#pragma unroll
        for (int off = 16; off; off >>= 1)
            m = fmaxf(m, __shfl_xor_sync(0xffffffffu, m, off));

        float ex0 = (lane < cnt)      ? __expf(e0 - m) : 0.0f;
        float ex1 = (lane + 32 < cnt) ? __expf(e1 - m) : 0.0f;
        float sum = ex0 + ex1;
#pragma unroll
        for (int off = 16; off; off >>= 1)
            sum += __shfl_xor_sync(0xffffffffu, sum, off);
        const float inv = 1.0f / sum;

        stage[warp][lane]      = make_float2(ex0 * inv, __int_as_float(s0));
        stage[warp][lane + 32] = make_float2(ex1 * inv, __int_as_float(s1));
        __syncwarp();

        const uint2* Whh = (const uint2*)g_Whh;   // 8B = 4 halfs per lane
        int i = 0;
        for (; i + 4 <= cnt; i += 4) {
            float2 p0 = stage[warp][i + 0];
            float2 p1 = stage[warp][i + 1];
            float2 p2 = stage[warp][i + 2];
            float2 p3 = stage[warp][i + 3];
            uint2 u0 = Whh[__float_as_int(p0.y) * 32 + lane];
            uint2 u1 = Whh[__float_as_int(p1.y) * 32 + lane];
            uint2 u2 = Whh[__float_as_int(p2.y) * 32 + lane];
            uint2 u3 = Whh[__float_as_int(p3.y) * 32 + lane];
#define ACC(u, al)                                                         \
            {                                                              \
                float2 lo = __half22float2(*(__half2*)&(u).x);             \
                float2 hi = __half22float2(*(__half2*)&(u).y);             \
                acc.x = fmaf((al), lo.x, acc.x);                           \
                acc.y = fmaf((al), lo.y, acc.y);                           \
                acc.z = fmaf((al), hi.x, acc.z);                           \
                acc.w = fmaf((al), hi.y, acc.w);                           \
            }
            ACC(u0, p0.x) ACC(u1, p1.x) ACC(u2, p2.x) ACC(u3, p3.x)
        }
        for (; i < cnt; i++) {
            float2 p = stage[warp][i];
            uint2 u = Whh[__float_as_int(p.y) * 32 + lane];
            ACC(u, p.x)
        }
#undef ACC
    }

    ((float4*)out)[v * 32 + lane] = acc;
}

// ---------------------------------------------------------------------------
extern "C" void kernel_launch(void* const* d_in, const int* in_sizes, int n_in,
                              void* d_out, int out_size) {
    const float* h   = (const float*)d_in[0];
    const float* W   = (const float*)d_in[1];
    const float* a   = (const float*)d_in[2];
    const int*   src = (const int*)d_in[3];
    const int*   dst = (const int*)d_in[4];
    float*       out = (float*)d_out;

    k_reset<<<(Nn + 255) / 256, 256>>>();
    k_build<<<GEMM_BLOCKS * 2, 128>>>(h, W, a, (const int4*)src, (const int4*)dst);
    k_node <<<(Nn + 7) / 8, 256>>>(h, out);
}